// round 15
// baseline (speedup 1.0000x reference)
#include <cuda_runtime.h>
#include <cuda_bf16.h>
#include <cstdint>

// FracDownSample fused kernel v13 (sm_103a) = v9 (best, 104.6us) + register-
// safe packed f32x2 FMA phase 4 (j=2 grouping: 8 doubles of accumulator live,
// v9's footprint; v12's 32-reg accumulator spill fixed).
// x:[16,256,128,128] f32, w_key:[64,256], w_sim:[4,64] -> out:[16,256,64,64] f32

#define H_ 128
#define W_ 128
#define C_ 256
#define HW (H_ * W_)
#define KQ_STRIDE 5

#define BP_WORDS   8192          // 8 c2-blocks * 8 ntiles * 128 words (uint4 B)
#define PCH_WORDS  1024          // packed bf16x2 chunk (16 ch)
#define RAW_WORDS  2048          // raw f32 chunk (16 ch * 128 px)

__device__ __forceinline__ uint32_t packbf(float lo, float hi) {
    __nv_bfloat162 v = __floats2bfloat162_rn(lo, hi);
    return *reinterpret_cast<uint32_t*>(&v);
}
__device__ __forceinline__ void cp_async16(uint32_t smem_addr, const void* gptr) {
    asm volatile("cp.async.cg.shared.global [%0], [%1], 16;"
                 :: "r"(smem_addr), "l"(gptr) : "memory");
}
__device__ __forceinline__ void cp_commit() {
    asm volatile("cp.async.commit_group;" ::: "memory");
}
template <int N>
__device__ __forceinline__ void cp_wait() {
    asm volatile("cp.async.wait_group %0;" :: "n"(N) : "memory");
}
// packed f32x2 fma: acc(lo,hi) += v(lo,hi) * w(lo,hi)
#define FMA2(acc, v, w) \
    asm("fma.rn.f32x2 %0, %1, %2, %0;" : "+d"(acc) : "d"(v), "d"(w))

__global__ __launch_bounds__(256, 3)
void frac_downsample_kernel(const float* __restrict__ x,
                            const float* __restrict__ w_key,
                            const float* __restrict__ w_sim,
                            float* __restrict__ out) {
    extern __shared__ uint32_t smem[];
    uint32_t* Bp     = smem;                            // 32 KB
    uint32_t* Pk     = Bp + BP_WORDS;                   // 2 * 4 KB packed ring
    float*    Raw    = (float*)(Pk + 2 * PCH_WORDS);    // 3 * 8 KB raw ring
    float*    kq2    = Raw + 3 * RAW_WORDS;             // 2 planes * 128*5
    float*    wsim_s = kq2 + 2 * 128 * KQ_STRIDE;       // 256
    float*    aw     = wsim_s + 256;                    // 512, 16B-aligned (awp)

    const int tid = threadIdx.x;
    const int bid = blockIdx.x;
    const int n  = bid >> 7;
    const int hb = (bid >> 2) & 31;
    const int wq = bid & 3;

    const float* xbase = x + ((size_t)n * C_ * H_ + (size_t)hb * 4) * W_ + wq * 32;

    // ---- cp.async geometry: thread copies uint4 u = tid and tid+256 ----
    const int u0 = tid, u1 = tid + 256;
    const size_t cg0 = (size_t)(u0 >> 5) * HW + ((u0 & 31) >> 3) * W_ + (u0 & 7) * 4;
    const size_t cg1 = (size_t)(u1 >> 5) * HW + ((u1 & 31) >> 3) * W_ + (u1 & 7) * 4;
    uint32_t raw_s0[3], raw_s1[3];
    #pragma unroll
    for (int r = 0; r < 3; r++) {
        raw_s0[r] = (uint32_t)__cvta_generic_to_shared(Raw + r * RAW_WORDS + u0 * 4);
        raw_s1[r] = (uint32_t)__cvta_generic_to_shared(Raw + r * RAW_WORDS + u1 * 4);
    }

    // ---- issue chunks 0,1,2 ----
    #pragma unroll
    for (int ck = 0; ck < 3; ck++) {
        const float* xc = xbase + (size_t)ck * (16 * HW);
        cp_async16(raw_s0[ck], xc + cg0);
        cp_async16(raw_s1[ck], xc + cg1);
        cp_commit();
    }

    // ---- stage B (w_key): 2-kstep uint4 blocks of bf16x2 fragments ----
    {
        const int c    = (tid & 127) * 2;
        const int s    = c >> 4;
        const int kkc  = c & 15;
        const int tigc = (kkc >> 1) & 3;
        const int kh   = kkc >> 3;
        const int rb   = tid >> 7;
        const int base = ((s >> 1) * 8) * 128 + (s & 1) * 2 + kh;
        #pragma unroll 8
        for (int rr = 0; rr < 32; rr++) {
            int r = rr * 2 + rb;
            int nt = r >> 3, g = r & 7;
            Bp[base + nt * 128 + (g * 4 + tigc) * 4] =
                packbf(w_key[r * 256 + c], w_key[r * 256 + c + 1]);
        }
    }
    wsim_s[tid] = w_sim[tid];

    // ---- pack geometry: thread owns pixel pair + channel pairs ----
    const int cpair = tid >> 6;                 // 0..3
    const int pix2  = (tid & 63) * 2;
    const int rch0 = 2 * cpair;
    const int rch1 = 2 * cpair + 8;
    int sw[4];
    {
        const int mtile = pix2 >> 4;
        #pragma unroll
        for (int j = 0; j < 2; j++) {
            int ml = (pix2 + j) & 15;
            int gid_s = ml & 7, b1 = ml >> 3;
            int lane_r = ((gid_s * 4 + cpair) + mtile * 2) & 31;
            int off = lane_r * 2 + b1;
            sw[j]     = mtile * 128 + off;
            sw[2 + j] = mtile * 128 + 64 + off;
        }
    }

    // ---- prologue: pack chunk 0 ----
    cp_wait<2>();
    __syncthreads();
    {
        const float* rb0 = Raw;
        float2 l0 = *(const float2*)(rb0 + rch0 * 128 + pix2);
        float2 h0 = *(const float2*)(rb0 + (rch0 + 1) * 128 + pix2);
        float2 l1 = *(const float2*)(rb0 + rch1 * 128 + pix2);
        float2 h1 = *(const float2*)(rb0 + (rch1 + 1) * 128 + pix2);
        Pk[sw[0]] = packbf(l0.x, h0.x);
        Pk[sw[1]] = packbf(l0.y, h0.y);
        Pk[sw[2]] = packbf(l1.x, h1.x);
        Pk[sw[3]] = packbf(l1.y, h1.y);
    }

    const int warp = tid >> 5, lane = tid & 31;
    const int warp_m = warp & 3;
    const int warp_n = warp >> 2;
    const int gid = lane >> 2, tig = lane & 3;

    float acc[2][4][4];
    #pragma unroll
    for (int a = 0; a < 2; a++)
        #pragma unroll
        for (int b = 0; b < 4; b++)
            acc[a][b][0] = acc[a][b][1] = acc[a][b][2] = acc[a][b][3] = 0.f;

    // ---- Phase 1: 16 ksteps; cp.async 3 ahead, pack 1 ahead ----
    uint4 bq[4];
    static const int mod3[19] = {0,1,2,0,1,2,0,1,2,0,1,2,0,1,2,0,1,2,0};
    #pragma unroll
    for (int c = 0; c < 16; c++) {
        cp_wait<1>();
        __syncthreads();
        if (c + 3 < 16) {
            const float* xc = xbase + (size_t)(c + 3) * (16 * HW);
            int slot = mod3[c + 3];
            cp_async16(raw_s0[slot], xc + cg0);
            cp_async16(raw_s1[slot], xc + cg1);
        }
        cp_commit();   // unconditional: keeps the wait-window arithmetic valid
        if (c + 1 < 16) {
            const float* rb = Raw + mod3[c + 1] * RAW_WORDS;
            float2 l0 = *(const float2*)(rb + rch0 * 128 + pix2);
            float2 h0 = *(const float2*)(rb + (rch0 + 1) * 128 + pix2);
            float2 l1 = *(const float2*)(rb + rch1 * 128 + pix2);
            float2 h1 = *(const float2*)(rb + (rch1 + 1) * 128 + pix2);
            uint32_t* Pn = Pk + ((c + 1) & 1) * PCH_WORDS;
            Pn[sw[0]] = packbf(l0.x, h0.x);
            Pn[sw[1]] = packbf(l0.y, h0.y);
            Pn[sw[2]] = packbf(l1.x, h1.x);
            Pn[sw[3]] = packbf(l1.y, h1.y);
        }
        if ((c & 1) == 0) {
            #pragma unroll
            for (int ntl = 0; ntl < 4; ntl++)
                bq[ntl] = *(const uint4*)(
                    Bp + ((c >> 1) * 8 + warp_n * 4 + ntl) * 128 + lane * 4);
        }
        const uint32_t* Ac = Pk + (c & 1) * PCH_WORDS;
        uint2 afr[2][2];
        #pragma unroll
        for (int mtl = 0; mtl < 2; mtl++) {
            int mt = warp_m * 2 + mtl;
            int lr = ((lane + mt * 2) & 31) * 2;
            afr[mtl][0] = *reinterpret_cast<const uint2*>(Ac + mt * 128 + lr);
            afr[mtl][1] = *reinterpret_cast<const uint2*>(Ac + mt * 128 + 64 + lr);
        }
        #pragma unroll
        for (int mtl = 0; mtl < 2; mtl++)
            #pragma unroll
            for (int ntl = 0; ntl < 4; ntl++) {
                uint32_t bx = (c & 1) ? bq[ntl].z : bq[ntl].x;
                uint32_t by = (c & 1) ? bq[ntl].w : bq[ntl].y;
                asm volatile(
                    "mma.sync.aligned.m16n8k16.row.col.f32.bf16.bf16.f32 "
                    "{%0,%1,%2,%3}, {%4,%5,%6,%7}, {%8,%9}, {%0,%1,%2,%3};"
                    : "+f"(acc[mtl][ntl][0]), "+f"(acc[mtl][ntl][1]),
                      "+f"(acc[mtl][ntl][2]), "+f"(acc[mtl][ntl][3])
                    : "r"(afr[mtl][0].x), "r"(afr[mtl][0].y),
                      "r"(afr[mtl][1].x), "r"(afr[mtl][1].y),
                      "r"(bx), "r"(by));
            }
    }
    __syncthreads();

    // ---- Phase 2: kq = w_sim * relu(key) ----
    #pragma unroll
    for (int mtl = 0; mtl < 2; mtl++) {
        float pa[4] = {0, 0, 0, 0}, pb[4] = {0, 0, 0, 0};
        #pragma unroll
        for (int ntl = 0; ntl < 4; ntl++) {
            int col0 = warp_n * 32 + ntl * 8 + 2 * tig;
            float v0 = fmaxf(acc[mtl][ntl][0], 0.f);
            float v1 = fmaxf(acc[mtl][ntl][1], 0.f);
            float v2 = fmaxf(acc[mtl][ntl][2], 0.f);
            float v3 = fmaxf(acc[mtl][ntl][3], 0.f);
            #pragma unroll
            for (int s = 0; s < 4; s++) {
                float w0 = wsim_s[s * 64 + col0];
                float w1 = wsim_s[s * 64 + col0 + 1];
                pa[s] += v0 * w0 + v1 * w1;
                pb[s] += v2 * w0 + v3 * w1;
            }
        }
        #pragma unroll
        for (int s = 0; s < 4; s++) {
            pa[s] += __shfl_xor_sync(0xffffffffu, pa[s], 1);
            pa[s] += __shfl_xor_sync(0xffffffffu, pa[s], 2);
            pb[s] += __shfl_xor_sync(0xffffffffu, pb[s], 1);
            pb[s] += __shfl_xor_sync(0xffffffffu, pb[s], 2);
        }
        float va = (tig == 0) ? pa[0] : (tig == 1) ? pa[1] : (tig == 2) ? pa[2] : pa[3];
        float vb = (tig == 0) ? pb[0] : (tig == 1) ? pb[1] : (tig == 2) ? pb[2] : pb[3];
        int r0 = warp_m * 32 + mtl * 16 + gid;
        float* plane = kq2 + warp_n * 128 * KQ_STRIDE;
        plane[r0 * KQ_STRIDE + tig]       = va;
        plane[(r0 + 8) * KQ_STRIDE + tig] = vb;
    }
    __syncthreads();

    // ---- Phase 3: per-window softmax; transposed layout:
    //      aw[(i*8 + win)*16 + slot(q)*4 + col], slot(q) = (q + (win>>1)) & 3
    if (tid < 32) {
        int win = tid >> 2, s = tid & 3;
        float vals[16];
        float mx = -3.4e38f;
        #pragma unroll
        for (int p = 0; p < 16; p++) {
            int mm = (p >> 2) * 32 + win * 4 + (p & 3);
            float v = (kq2[mm * KQ_STRIDE + s] +
                       kq2[128 * KQ_STRIDE + mm * KQ_STRIDE + s]) * 0.25f;
            vals[p] = v;
            mx = fmaxf(mx, v);
        }
        float sum = 0.f;
        #pragma unroll
        for (int p = 0; p < 16; p++) { vals[p] = __expf(vals[p] - mx); sum += vals[p]; }
        float inv = 1.f / sum;
        const int slot = ((s + (win >> 1)) & 3) * 4;
        #pragma unroll
        for (int p = 0; p < 16; p++)
            aw[((p >> 2) * 8 + win) * 16 + slot + (p & 3)] = vals[p] * inv;
    }
    __syncthreads();

    // ---- Phase 4: FMA2 aggregation, j=2 grouping (8 live accumulator
    //      doubles = v9's register footprint) ----
    {
        const int win = tid & 7;
        const int cb  = tid >> 3;               // 0..31
        const float* xa = x + (size_t)n * C_ * HW + (size_t)(hb * 4) * W_
                          + wq * 32 + win * 4 + (size_t)cb * HW;
        float* obase = out + ((size_t)n * C_ * 64 + hb * 2) * 64 + wq * 16 + win * 2
                     + (size_t)cb * 4096;
        const float* awin = aw + win * 16;
        const int ws = win >> 1;
        const int q0 = ((0 + ws) & 3) * 4;
        const int q1 = ((1 + ws) & 3) * 4;
        const int q2 = ((2 + ws) & 3) * 4;
        const int q3 = ((3 + ws) & 3) * 4;
        #pragma unroll
        for (int g = 0; g < 4; g++) {
            const float* xp = xa + (size_t)(g * 64) * HW;   // channels cb+g*64, +32
            double o2[2][4];
            #pragma unroll
            for (int j = 0; j < 2; j++)
                o2[j][0] = o2[j][1] = o2[j][2] = o2[j][3] = 0.0;
            #pragma unroll
            for (int i = 0; i < 4; i++) {
                const float* ab = awin + i * 128;
                double2 w0 = *(const double2*)(ab + q0);
                double2 w1 = *(const double2*)(ab + q1);
                double2 w2 = *(const double2*)(ab + q2);
                double2 w3 = *(const double2*)(ab + q3);
                #pragma unroll
                for (int j = 0; j < 2; j++) {
                    double2 v = *(const double2*)(
                        xp + (size_t)(j * 32) * HW + i * W_);
                    FMA2(o2[j][0], v.x, w0.x); FMA2(o2[j][0], v.y, w0.y);
                    FMA2(o2[j][1], v.x, w1.x); FMA2(o2[j][1], v.y, w1.y);
                    FMA2(o2[j][2], v.x, w2.x); FMA2(o2[j][2], v.y, w2.y);
                    FMA2(o2[j][3], v.x, w3.x); FMA2(o2[j][3], v.y, w3.y);
                }
            }
            #pragma unroll
            for (int j = 0; j < 2; j++) {
                float2 f0 = *reinterpret_cast<float2*>(&o2[j][0]);
                float2 f1 = *reinterpret_cast<float2*>(&o2[j][1]);
                float2 f2 = *reinterpret_cast<float2*>(&o2[j][2]);
                float2 f3 = *reinterpret_cast<float2*>(&o2[j][3]);
                float r0 = f0.x + f0.y;
                float r1 = f1.x + f1.y;
                float r2 = f2.x + f2.y;
                float r3 = f3.x + f3.y;
                float* op = obase + (size_t)(g * 64 + j * 32) * 4096;
                *reinterpret_cast<float2*>(op)      = make_float2(r0, r1);
                *reinterpret_cast<float2*>(op + 64) = make_float2(r2, r3);
            }
        }
    }
}

extern "C" void kernel_launch(void* const* d_in, const int* in_sizes, int n_in,
                              void* d_out, int out_size) {
    const float* x  = (const float*)d_in[0];
    const float* wk = (const float*)d_in[1];
    const float* ws = (const float*)d_in[2];
    float* out = (float*)d_out;

    const int smem_bytes = (BP_WORDS + 2 * PCH_WORDS + 3 * RAW_WORDS) * 4
                         + (2 * 128 * KQ_STRIDE + 256 + 512) * 4;   // 73728 B
    cudaFuncSetAttribute(frac_downsample_kernel,
                         cudaFuncAttributeMaxDynamicSharedMemorySize, smem_bytes);

    frac_downsample_kernel<<<2048, 256, smem_bytes>>>(x, wk, ws, out);
}

// round 16
// speedup vs baseline: 1.5268x; 1.5268x over previous
#include <cuda_runtime.h>
#include <cuda_bf16.h>
#include <cstdint>

// FracDownSample fused kernel v14 (sm_103a) = v9 (best, 104.6us) with the
// B-fragment LDS hoisted above the cp.async wait + barrier (overlaps the
// 29-cyc LDS latency with the barrier instead of the first MMA).
// x:[16,256,128,128] f32, w_key:[64,256], w_sim:[4,64] -> out:[16,256,64,64] f32

#define H_ 128
#define W_ 128
#define C_ 256
#define HW (H_ * W_)
#define KQ_STRIDE 5

#define BP_WORDS   8192          // 8 c2-blocks * 8 ntiles * 128 words (uint4 B)
#define PCH_WORDS  1024          // packed bf16x2 chunk (16 ch)
#define RAW_WORDS  2048          // raw f32 chunk (16 ch * 128 px)

__device__ __forceinline__ uint32_t packbf(float lo, float hi) {
    __nv_bfloat162 v = __floats2bfloat162_rn(lo, hi);
    return *reinterpret_cast<uint32_t*>(&v);
}
__device__ __forceinline__ void cp_async16(uint32_t smem_addr, const void* gptr) {
    asm volatile("cp.async.cg.shared.global [%0], [%1], 16;"
                 :: "r"(smem_addr), "l"(gptr) : "memory");
}
__device__ __forceinline__ void cp_commit() {
    asm volatile("cp.async.commit_group;" ::: "memory");
}
template <int N>
__device__ __forceinline__ void cp_wait() {
    asm volatile("cp.async.wait_group %0;" :: "n"(N) : "memory");
}

__global__ __launch_bounds__(256, 3)
void frac_downsample_kernel(const float* __restrict__ x,
                            const float* __restrict__ w_key,
                            const float* __restrict__ w_sim,
                            float* __restrict__ out) {
    extern __shared__ uint32_t smem[];
    uint32_t* Bp     = smem;                            // 32 KB
    uint32_t* Pk     = Bp + BP_WORDS;                   // 2 * 4 KB packed ring
    float*    Raw    = (float*)(Pk + 2 * PCH_WORDS);    // 3 * 8 KB raw ring
    float*    kq2    = Raw + 3 * RAW_WORDS;             // 2 planes * 128*5
    float*    wsim_s = kq2 + 2 * 128 * KQ_STRIDE;       // 256
    float*    aw     = wsim_s + 256;                    // 512, 16B-aligned

    const int tid = threadIdx.x;
    const int bid = blockIdx.x;
    const int n  = bid >> 7;
    const int hb = (bid >> 2) & 31;
    const int wq = bid & 3;

    const float* xbase = x + ((size_t)n * C_ * H_ + (size_t)hb * 4) * W_ + wq * 32;

    // ---- cp.async geometry: thread copies uint4 u = tid and tid+256 ----
    const int u0 = tid, u1 = tid + 256;
    const size_t cg0 = (size_t)(u0 >> 5) * HW + ((u0 & 31) >> 3) * W_ + (u0 & 7) * 4;
    const size_t cg1 = (size_t)(u1 >> 5) * HW + ((u1 & 31) >> 3) * W_ + (u1 & 7) * 4;
    uint32_t raw_s0[3], raw_s1[3];
    #pragma unroll
    for (int r = 0; r < 3; r++) {
        raw_s0[r] = (uint32_t)__cvta_generic_to_shared(Raw + r * RAW_WORDS + u0 * 4);
        raw_s1[r] = (uint32_t)__cvta_generic_to_shared(Raw + r * RAW_WORDS + u1 * 4);
    }

    // ---- issue chunks 0,1,2 ----
    #pragma unroll
    for (int ck = 0; ck < 3; ck++) {
        const float* xc = xbase + (size_t)ck * (16 * HW);
        cp_async16(raw_s0[ck], xc + cg0);
        cp_async16(raw_s1[ck], xc + cg1);
        cp_commit();
    }

    // ---- stage B (w_key): 2-kstep uint4 blocks of bf16x2 fragments ----
    {
        const int c    = (tid & 127) * 2;
        const int s    = c >> 4;
        const int kkc  = c & 15;
        const int tigc = (kkc >> 1) & 3;
        const int kh   = kkc >> 3;
        const int rb   = tid >> 7;
        const int base = ((s >> 1) * 8) * 128 + (s & 1) * 2 + kh;
        #pragma unroll 8
        for (int rr = 0; rr < 32; rr++) {
            int r = rr * 2 + rb;
            int nt = r >> 3, g = r & 7;
            Bp[base + nt * 128 + (g * 4 + tigc) * 4] =
                packbf(w_key[r * 256 + c], w_key[r * 256 + c + 1]);
        }
    }
    wsim_s[tid] = w_sim[tid];

    // ---- pack geometry: thread owns pixel pair + channel pairs ----
    const int cpair = tid >> 6;                 // 0..3
    const int pix2  = (tid & 63) * 2;
    const int rch0 = 2 * cpair;
    const int rch1 = 2 * cpair + 8;
    int sw[4];
    {
        const int mtile = pix2 >> 4;
        #pragma unroll
        for (int j = 0; j < 2; j++) {
            int ml = (pix2 + j) & 15;
            int gid_s = ml & 7, b1 = ml >> 3;
            int lane_r = ((gid_s * 4 + cpair) + mtile * 2) & 31;
            int off = lane_r * 2 + b1;
            sw[j]     = mtile * 128 + off;
            sw[2 + j] = mtile * 128 + 64 + off;
        }
    }

    // ---- prologue: pack chunk 0 ----
    cp_wait<2>();
    __syncthreads();
    {
        const float* rb0 = Raw;
        float2 l0 = *(const float2*)(rb0 + rch0 * 128 + pix2);
        float2 h0 = *(const float2*)(rb0 + (rch0 + 1) * 128 + pix2);
        float2 l1 = *(const float2*)(rb0 + rch1 * 128 + pix2);
        float2 h1 = *(const float2*)(rb0 + (rch1 + 1) * 128 + pix2);
        Pk[sw[0]] = packbf(l0.x, h0.x);
        Pk[sw[1]] = packbf(l0.y, h0.y);
        Pk[sw[2]] = packbf(l1.x, h1.x);
        Pk[sw[3]] = packbf(l1.y, h1.y);
    }

    const int warp = tid >> 5, lane = tid & 31;
    const int warp_m = warp & 3;
    const int warp_n = warp >> 2;
    const int gid = lane >> 2, tig = lane & 3;

    float acc[2][4][4];
    #pragma unroll
    for (int a = 0; a < 2; a++)
        #pragma unroll
        for (int b = 0; b < 4; b++)
            acc[a][b][0] = acc[a][b][1] = acc[a][b][2] = acc[a][b][3] = 0.f;

    // ---- Phase 1: 16 ksteps; cp.async 3 ahead, pack 1 ahead.
    //      B-fragment loads hoisted ABOVE the wait/barrier (Bp is immutable
    //      after the prologue) so their latency overlaps the barrier. ----
    uint4 bq[4];
    static const int mod3[19] = {0,1,2,0,1,2,0,1,2,0,1,2,0,1,2,0,1,2,0};
    #pragma unroll
    for (int c = 0; c < 16; c++) {
        if ((c & 1) == 0) {
            #pragma unroll
            for (int ntl = 0; ntl < 4; ntl++)
                bq[ntl] = *(const uint4*)(
                    Bp + ((c >> 1) * 8 + warp_n * 4 + ntl) * 128 + lane * 4);
        }
        cp_wait<1>();
        __syncthreads();
        if (c + 3 < 16) {
            const float* xc = xbase + (size_t)(c + 3) * (16 * HW);
            int slot = mod3[c + 3];
            cp_async16(raw_s0[slot], xc + cg0);
            cp_async16(raw_s1[slot], xc + cg1);
        }
        cp_commit();   // unconditional: keeps the wait-window arithmetic valid
        if (c + 1 < 16) {
            const float* rb = Raw + mod3[c + 1] * RAW_WORDS;
            float2 l0 = *(const float2*)(rb + rch0 * 128 + pix2);
            float2 h0 = *(const float2*)(rb + (rch0 + 1) * 128 + pix2);
            float2 l1 = *(const float2*)(rb + rch1 * 128 + pix2);
            float2 h1 = *(const float2*)(rb + (rch1 + 1) * 128 + pix2);
            uint32_t* Pn = Pk + ((c + 1) & 1) * PCH_WORDS;
            Pn[sw[0]] = packbf(l0.x, h0.x);
            Pn[sw[1]] = packbf(l0.y, h0.y);
            Pn[sw[2]] = packbf(l1.x, h1.x);
            Pn[sw[3]] = packbf(l1.y, h1.y);
        }
        const uint32_t* Ac = Pk + (c & 1) * PCH_WORDS;
        uint2 afr[2][2];
        #pragma unroll
        for (int mtl = 0; mtl < 2; mtl++) {
            int mt = warp_m * 2 + mtl;
            int lr = ((lane + mt * 2) & 31) * 2;
            afr[mtl][0] = *reinterpret_cast<const uint2*>(Ac + mt * 128 + lr);
            afr[mtl][1] = *reinterpret_cast<const uint2*>(Ac + mt * 128 + 64 + lr);
        }
        #pragma unroll
        for (int mtl = 0; mtl < 2; mtl++)
            #pragma unroll
            for (int ntl = 0; ntl < 4; ntl++) {
                uint32_t bx = (c & 1) ? bq[ntl].z : bq[ntl].x;
                uint32_t by = (c & 1) ? bq[ntl].w : bq[ntl].y;
                asm volatile(
                    "mma.sync.aligned.m16n8k16.row.col.f32.bf16.bf16.f32 "
                    "{%0,%1,%2,%3}, {%4,%5,%6,%7}, {%8,%9}, {%0,%1,%2,%3};"
                    : "+f"(acc[mtl][ntl][0]), "+f"(acc[mtl][ntl][1]),
                      "+f"(acc[mtl][ntl][2]), "+f"(acc[mtl][ntl][3])
                    : "r"(afr[mtl][0].x), "r"(afr[mtl][0].y),
                      "r"(afr[mtl][1].x), "r"(afr[mtl][1].y),
                      "r"(bx), "r"(by));
            }
    }
    __syncthreads();

    // ---- Phase 2: kq = w_sim * relu(key) ----
    #pragma unroll
    for (int mtl = 0; mtl < 2; mtl++) {
        float pa[4] = {0, 0, 0, 0}, pb[4] = {0, 0, 0, 0};
        #pragma unroll
        for (int ntl = 0; ntl < 4; ntl++) {
            int col0 = warp_n * 32 + ntl * 8 + 2 * tig;
            float v0 = fmaxf(acc[mtl][ntl][0], 0.f);
            float v1 = fmaxf(acc[mtl][ntl][1], 0.f);
            float v2 = fmaxf(acc[mtl][ntl][2], 0.f);
            float v3 = fmaxf(acc[mtl][ntl][3], 0.f);
            #pragma unroll
            for (int s = 0; s < 4; s++) {
                float w0 = wsim_s[s * 64 + col0];
                float w1 = wsim_s[s * 64 + col0 + 1];
                pa[s] += v0 * w0 + v1 * w1;
                pb[s] += v2 * w0 + v3 * w1;
            }
        }
        #pragma unroll
        for (int s = 0; s < 4; s++) {
            pa[s] += __shfl_xor_sync(0xffffffffu, pa[s], 1);
            pa[s] += __shfl_xor_sync(0xffffffffu, pa[s], 2);
            pb[s] += __shfl_xor_sync(0xffffffffu, pb[s], 1);
            pb[s] += __shfl_xor_sync(0xffffffffu, pb[s], 2);
        }
        float va = (tig == 0) ? pa[0] : (tig == 1) ? pa[1] : (tig == 2) ? pa[2] : pa[3];
        float vb = (tig == 0) ? pb[0] : (tig == 1) ? pb[1] : (tig == 2) ? pb[2] : pb[3];
        int r0 = warp_m * 32 + mtl * 16 + gid;
        float* plane = kq2 + warp_n * 128 * KQ_STRIDE;
        plane[r0 * KQ_STRIDE + tig]       = va;
        plane[(r0 + 8) * KQ_STRIDE + tig] = vb;
    }
    __syncthreads();

    // ---- Phase 3: per-window softmax; output to aw[(p*8+win)*4+q] ----
    if (tid < 32) {
        int win = tid >> 2, s = tid & 3;
        float vals[16];
        float mx = -3.4e38f;
        #pragma unroll
        for (int p = 0; p < 16; p++) {
            int mm = (p >> 2) * 32 + win * 4 + (p & 3);
            float v = (kq2[mm * KQ_STRIDE + s] +
                       kq2[128 * KQ_STRIDE + mm * KQ_STRIDE + s]) * 0.25f;
            vals[p] = v;
            mx = fmaxf(mx, v);
        }
        float sum = 0.f;
        #pragma unroll
        for (int p = 0; p < 16; p++) { vals[p] = __expf(vals[p] - mx); sum += vals[p]; }
        float inv = 1.f / sum;
        #pragma unroll
        for (int p = 0; p < 16; p++)
            aw[(p * 8 + win) * 4 + s] = vals[p] * inv;
    }
    __syncthreads();

    // ---- Phase 4: aggregation, 4 channel-passes per weight load (v9) ----
    {
        const int win = tid & 7;
        const int cb  = tid >> 3;
        const float* xa = x + (size_t)n * C_ * HW + (size_t)(hb * 4) * W_
                          + wq * 32 + win * 4 + (size_t)cb * HW;
        float* obase = out + ((size_t)n * C_ * 64 + hb * 2) * 64 + wq * 16 + win * 2
                     + (size_t)cb * 4096;
        const float* awin = aw + win * 4;
        #pragma unroll
        for (int pp = 0; pp < 2; pp++) {
            const float* xp = xa + (size_t)(pp * 128) * HW;
            float o[4][4];
            #pragma unroll
            for (int j = 0; j < 4; j++)
                o[j][0] = o[j][1] = o[j][2] = o[j][3] = 0.f;
            #pragma unroll
            for (int i = 0; i < 4; i++) {
                float4 w0 = *reinterpret_cast<const float4*>(awin + (i * 4 + 0) * 32);
                float4 w1 = *reinterpret_cast<const float4*>(awin + (i * 4 + 1) * 32);
                float4 w2 = *reinterpret_cast<const float4*>(awin + (i * 4 + 2) * 32);
                float4 w3 = *reinterpret_cast<const float4*>(awin + (i * 4 + 3) * 32);
                float4 v0 = *reinterpret_cast<const float4*>(xp + i * W_);
                float4 v1 = *reinterpret_cast<const float4*>(xp + (size_t)32 * HW + i * W_);
                float4 v2 = *reinterpret_cast<const float4*>(xp + (size_t)64 * HW + i * W_);
                float4 v3 = *reinterpret_cast<const float4*>(xp + (size_t)96 * HW + i * W_);
                o[0][0] += v0.x * w0.x + v0.y * w1.x + v0.z * w2.x + v0.w * w3.x;
                o[0][1] += v0.x * w0.y + v0.y * w1.y + v0.z * w2.y + v0.w * w3.y;
                o[0][2] += v0.x * w0.z + v0.y * w1.z + v0.z * w2.z + v0.w * w3.z;
                o[0][3] += v0.x * w0.w + v0.y * w1.w + v0.z * w2.w + v0.w * w3.w;
                o[1][0] += v1.x * w0.x + v1.y * w1.x + v1.z * w2.x + v1.w * w3.x;
                o[1][1] += v1.x * w0.y + v1.y * w1.y + v1.z * w2.y + v1.w * w3.y;
                o[1][2] += v1.x * w0.z + v1.y * w1.z + v1.z * w2.z + v1.w * w3.z;
                o[1][3] += v1.x * w0.w + v1.y * w1.w + v1.z * w2.w + v1.w * w3.w;
                o[2][0] += v2.x * w0.x + v2.y * w1.x + v2.z * w2.x + v2.w * w3.x;
                o[2][1] += v2.x * w0.y + v2.y * w1.y + v2.z * w2.y + v2.w * w3.y;
                o[2][2] += v2.x * w0.z + v2.y * w1.z + v2.z * w2.z + v2.w * w3.z;
                o[2][3] += v2.x * w0.w + v2.y * w1.w + v2.z * w2.w + v2.w * w3.w;
                o[3][0] += v3.x * w0.x + v3.y * w1.x + v3.z * w2.x + v3.w * w3.x;
                o[3][1] += v3.x * w0.y + v3.y * w1.y + v3.z * w2.y + v3.w * w3.y;
                o[3][2] += v3.x * w0.z + v3.y * w1.z + v3.z * w2.z + v3.w * w3.z;
                o[3][3] += v3.x * w0.w + v3.y * w1.w + v3.z * w2.w + v3.w * w3.w;
            }
            #pragma unroll
            for (int j = 0; j < 4; j++) {
                float* op = obase + (size_t)(pp * 128 + j * 32) * 4096;
                *reinterpret_cast<float2*>(op)      = make_float2(o[j][0], o[j][1]);
                *reinterpret_cast<float2*>(op + 64) = make_float2(o[j][2], o[j][3]);
            }
        }
    }
}

extern "C" void kernel_launch(void* const* d_in, const int* in_sizes, int n_in,
                              void* d_out, int out_size) {
    const float* x  = (const float*)d_in[0];
    const float* wk = (const float*)d_in[1];
    const float* ws = (const float*)d_in[2];
    float* out = (float*)d_out;

    const int smem_bytes = (BP_WORDS + 2 * PCH_WORDS + 3 * RAW_WORDS) * 4
                         + (2 * 128 * KQ_STRIDE + 256 + 512) * 4;   // 73728 B
    cudaFuncSetAttribute(frac_downsample_kernel,
                         cudaFuncAttributeMaxDynamicSharedMemorySize, smem_bytes);

    frac_downsample_kernel<<<2048, 256, smem_bytes>>>(x, wk, ws, out);
}